// round 17
// baseline (speedup 1.0000x reference)
#include <cuda_runtime.h>
#include <cuda_fp16.h>
#include <cstdint>

// Problem constants
#define Bv     4
#define Nv     2048
#define INF_   256
#define OUTF_  256
#define Hh     8
#define NHv    32
#define SLOPE  0.2f
#define LOG2E  1.4426950408889634f

// ---------------------------------------------------------------------------
// Device scratch (no allocations; zero-initialized at load)
// ---------------------------------------------------------------------------
__device__ float    g_wh1s [Bv * Hh * Nv];              // wh1 * log2e   [bh][n]
__device__ float    g_wh2s [Bv * Hh * Nv];              // wh2 * log2e   [bh][n]
__device__ unsigned g_w2maxU[Bv * Hh];                  // ordered-uint max (atomicMax)
__device__ unsigned g_adjbits[Bv * Nv * (Nv / 32)];     // 2 MB adj bitmask
__device__ __align__(16) __half g_Vh16[32 * 2048 * 32]; // 4 MB V f16, plain [bh][j][d]
__device__ __align__(16) uint32_t g_Wh16t[OUTF_ * 128]; // W^T f16 h2, k-interleaved [n][128w]
__device__ __align__(16) uint32_t g_Ah16[Bv * Nv * 128];// 4 MB h f16 h2, k-interleaved [m][128w]
__device__ __align__(16) float    g_U[INF_ * 16];       // U = W @ a_blocks

#define ONESH2 0x3C003C00u

// ---------------------------------------------------------------------------
// helpers
// ---------------------------------------------------------------------------
__device__ __forceinline__ float ex2f(float x) {
    float y; asm("ex2.approx.ftz.f32 %0, %1;" : "=f"(y) : "f"(x)); return y;
}
__device__ __forceinline__ uint32_t packh2(float a, float b) {
    __half2 h = __floats2half2_rn(a, b);
    return *reinterpret_cast<uint32_t*>(&h);
}
__device__ __forceinline__ uint32_t hmul2u(uint32_t a, uint32_t b) {
    uint32_t d; asm("mul.f16x2 %0, %1, %2;" : "=r"(d) : "r"(a), "r"(b)); return d;
}
__device__ __forceinline__ uint32_t hmax2u(uint32_t a, uint32_t b) {
    uint32_t d; asm("max.f16x2 %0, %1, %2;" : "=r"(d) : "r"(a), "r"(b)); return d;
}
__device__ __forceinline__ uint32_t prmtu(uint32_t a, uint32_t b, uint32_t c) {
    uint32_t d; asm("prmt.b32 %0, %1, %2, %3;" : "=r"(d) : "r"(a), "r"(b), "r"(c)); return d;
}
__device__ __forceinline__ uint32_t fkey(float f) {
    uint32_t u = __float_as_uint(f);
    return u ^ (uint32_t)(((int)u >> 31) | 0x80000000);
}
__device__ __forceinline__ float fkeyinv(uint32_t k) {
    return __uint_as_float(k ^ (((int)k >> 31) ? 0x80000000u : 0xFFFFFFFFu));
}
// interleaved word index for k-pair p within a 128-word row (A/W frag layout)
__device__ __forceinline__ int wordpos(int p) {
    int q = p & 7;
    int slot = ((q & 3) << 1) | (q >> 2);
    return ((p >> 3) << 3) + slot;
}
__device__ __forceinline__ int ipos(int j) {     // half index (F1/F2 rows)
    return wordpos(j >> 1) * 2 + (j & 1);
}
__device__ __forceinline__ uint32_t smem_u32(const void* p) {
    uint32_t a;
    asm("{ .reg .u64 t; cvta.to.shared.u64 t, %1; cvt.u32.u64 %0, t; }" : "=r"(a) : "l"(p));
    return a;
}
#define CP_ASYNC16(dst, src) \
    asm volatile("cp.async.cg.shared.global [%0], [%1], 16;" :: "r"(dst), "l"(src))
#define CP_COMMIT() asm volatile("cp.async.commit_group;" ::: "memory")
#define CP_WAIT2()  asm volatile("cp.async.wait_group 2;" ::: "memory")
#define LDSM4T(r0, r1, r2, r3, addr) \
    asm volatile("ldmatrix.sync.aligned.m8n8.x4.trans.shared.b16 {%0,%1,%2,%3}, [%4];" \
                 : "=r"(r0), "=r"(r1), "=r"(r2), "=r"(r3) : "r"(addr))

__device__ __forceinline__ void mma16816(float* d, uint32_t a0, uint32_t a1, uint32_t a2,
                                         uint32_t a3, uint32_t b0, uint32_t b1) {
    asm volatile(
        "mma.sync.aligned.m16n8k16.row.col.f32.f16.f16.f32 "
        "{%0,%1,%2,%3}, {%4,%5,%6,%7}, {%8,%9}, {%0,%1,%2,%3};"
        : "+f"(d[0]), "+f"(d[1]), "+f"(d[2]), "+f"(d[3])
        : "r"(a0), "r"(a1), "r"(a2), "r"(a3), "r"(b0), "r"(b1));
}

// ---------------------------------------------------------------------------
// K_u: blocks 0-7: U[k][c] from W and a.
//      blocks 8-15: W -> W^T f16 h2-packed, k-interleaved (g_Wh16t).
//      blocks 16-527: h -> f16 h2-packed, k-interleaved (g_Ah16), 16 rows/blk.
// ---------------------------------------------------------------------------
__global__ __launch_bounds__(256) void u_kernel(const float4* __restrict__ W4,
                                                const float* __restrict__ a_vec,
                                                const float4* __restrict__ h4) {
    __shared__ float sW[32][260];
    __shared__ float sa[64];
    const int bb = blockIdx.x, t = threadIdx.x;

    if (bb >= 16) {   // ---- hconv: 16 rows of h per block ----
        const int rb = (bb - 16) * 16;
#pragma unroll
        for (int i = 0; i < 4; i++) {
            int idx = t + i * 256;
            int row = rb + (idx >> 6), k4 = idx & 63;
            float4 v = h4[(size_t)row * 64 + k4];
            int p0 = k4 * 2;
            g_Ah16[(size_t)row * 128 + wordpos(p0)]     = packh2(v.x, v.y);
            g_Ah16[(size_t)row * 128 + wordpos(p0 + 1)] = packh2(v.z, v.w);
        }
        return;
    }

    if (t < 64 && bb < 8) sa[t] = a_vec[t];
    const int k0 = (bb & 7) * 32;
#pragma unroll
    for (int i = 0; i < 8; i++) {
        int idx4 = t + i * 256;
        int row = idx4 >> 6, col = (idx4 & 63) * 4;
        float4 v = W4[(size_t)k0 * 64 + idx4];
        *reinterpret_cast<float4*>(&sW[row][col]) = v;
    }
    __syncthreads();

    if (bb < 8) {
        const int k_loc = t >> 3, c8 = t & 7;
        float u1 = 0.f, u2 = 0.f;
#pragma unroll
        for (int d = 0; d < 32; d++) {
            float wv = sW[k_loc][c8 * 32 + d];
            u1 += wv * sa[d];
            u2 += wv * sa[32 + d];
        }
        g_U[(k0 + k_loc) * 16 + c8]     = u1;
        g_U[(k0 + k_loc) * 16 + 8 + c8] = u2;
    } else {
        const int n = t;
#pragma unroll
        for (int kp = 0; kp < 16; kp++) {
            uint32_t w = packh2(sW[2 * kp][n], sW[2 * kp + 1][n]);
            g_Wh16t[n * 128 + (k0 >> 4) * 8 + wordpos(kp)] = w;
        }
    }
}

// ---------------------------------------------------------------------------
// K_wh12: exact fp32 wh1/wh2 = h @ U (raw-view mapping); per-head wh2 max.
// ---------------------------------------------------------------------------
__global__ __launch_bounds__(256) void wh12_kernel(const float4* __restrict__ h4) {
    __shared__ float sH[16][260];
    __shared__ float sU[256][16];
    __shared__ float sred[8];
    const int t = threadIdx.x;
    const int r0 = blockIdx.x * 16;
#pragma unroll
    for (int i = 0; i < 4; i++) {
        int idx4 = t + i * 256;
        int row = idx4 >> 6, col = (idx4 & 63) * 4;
        float4 v = h4[(size_t)r0 * 64 + idx4];
        *reinterpret_cast<float4*>(&sH[row][col]) = v;
    }
#pragma unroll
    for (int i = 0; i < 4; i++) {
        int idx4 = t + i * 256;
        *reinterpret_cast<float4*>(&sU[0][0] + idx4 * 4) =
            *reinterpret_cast<const float4*>(g_U + idx4 * 4);
    }
    __syncthreads();

    const int row = t >> 4, out = t & 15;
    const float4* hrow = reinterpret_cast<const float4*>(&sH[row][0]);
    float acc = 0.f;
#pragma unroll 8
    for (int k4 = 0; k4 < 64; k4++) {
        float4 hv = hrow[k4];
        acc += hv.x * sU[k4 * 4 + 0][out];
        acc += hv.y * sU[k4 * 4 + 1][out];
        acc += hv.z * sU[k4 * 4 + 2][out];
        acc += hv.w * sU[k4 * 4 + 3][out];
    }
    acc *= LOG2E;

    const int r = r0 + row;
    const int b = r >> 11, hloc = (r & 2047) >> 8, bh = b * Hh + hloc;
    const int np = (r & 255) * 8 + (out & 7);
    if (out < 8) g_wh1s[bh * Nv + np] = acc;
    else         g_wh2s[bh * Nv + np] = acc;

    float mx = (out >= 8) ? acc : -1e30f;
#pragma unroll
    for (int o = 16; o > 0; o >>= 1) mx = fmaxf(mx, __shfl_xor_sync(0xFFFFFFFFu, mx, o));
    if ((t & 31) == 0) sred[t >> 5] = mx;
    __syncthreads();
    if (t == 0) {
        float m = sred[0];
#pragma unroll
        for (int q = 1; q < 8; q++) m = fmaxf(m, sred[q]);
        atomicMax(&g_w2maxU[bh], fkey(m));
    }
}

// ---------------------------------------------------------------------------
// K_adj: adj -> bitmask, PERSISTENT 296 blocks (2/SM) so compute-stream blocks
// can co-schedule. Grid-stride, 4 int4 loads in flight per iteration.
// ---------------------------------------------------------------------------
#define ADJ_BLOCKS 296
__global__ __launch_bounds__(256) void adjbits_kernel(const int4* __restrict__ adj4) {
    const unsigned stride = ADJ_BLOCKS * 256u;
    const unsigned total = 4194304u;          // 16.78M ints / 4
    unsigned base = blockIdx.x * 256u + threadIdx.x;
    const int lane8 = threadIdx.x & 7;
    const unsigned sh = lane8 * 4;

    for (unsigned i0 = base; i0 < total; i0 += stride * 4) {
        int4 v0 = adj4[i0];
        int4 v1 = (i0 + stride < total) ? adj4[i0 + stride] : make_int4(0, 0, 0, 0);
        int4 v2 = (i0 + 2 * stride < total) ? adj4[i0 + 2 * stride] : make_int4(0, 0, 0, 0);
        int4 v3 = (i0 + 3 * stride < total) ? adj4[i0 + 3 * stride] : make_int4(0, 0, 0, 0);
#pragma unroll
        for (int q = 0; q < 4; q++) {
            int4 v = (q == 0) ? v0 : (q == 1) ? v1 : (q == 2) ? v2 : v3;
            unsigned idx = i0 + q * stride;
            if (idx >= total) break;
            unsigned nib = (unsigned)(v.x > 0) | ((unsigned)(v.y > 0) << 1)
                         | ((unsigned)(v.z > 0) << 2) | ((unsigned)(v.w > 0) << 3);
            unsigned word = nib << sh;
            word |= __shfl_xor_sync(0xFFFFFFFFu, word, 1);
            word |= __shfl_xor_sync(0xFFFFFFFFu, word, 2);
            word |= __shfl_xor_sync(0xFFFFFFFFu, word, 4);
            if (lane8 == 0) g_adjbits[idx >> 3] = word;
        }
    }
}

// ---------------------------------------------------------------------------
// K1: f16 HMMA GEMM, 4-stage cp.async pipeline (BK=32/stage, 8 stages).
// Emits V f16 in plain [bh][j][d] layout (coalesced half2 stores).
// ---------------------------------------------------------------------------
__global__ __launch_bounds__(256) void gemm_f16_kernel() {
    __shared__ uint32_t sA[4][64][20];
    __shared__ uint32_t sB[4][64][20];

    const int tid = threadIdx.x;
    const int w = tid >> 5, lane = tid & 31;
    const int g = lane >> 2, tig = lane & 3;
    const int wr = w & 3, wc = w >> 2;
    const int mBase = blockIdx.x * 64, nBase = blockIdx.y * 64;

    float c[4][4];
#pragma unroll
    for (int nb = 0; nb < 4; nb++)
#pragma unroll
        for (int q = 0; q < 4; q++) c[nb][q] = 0.f;

    const int rowC = tid >> 2, qw = (tid & 3) * 4;
    const uint32_t dA0 = smem_u32(&sA[0][rowC][qw]);
    const uint32_t dB0 = smem_u32(&sB[0][rowC][qw]);
    const uint32_t* srcA = g_Ah16 + (size_t)(mBase + rowC) * 128 + qw;
    const uint32_t* srcB = g_Wh16t + (size_t)(nBase + rowC) * 128 + qw;
    const int STAGE_B = 64 * 20 * 4;

    const int rw = wr * 16, cw = wc * 32;
    const int tig2 = tig * 2;

#pragma unroll
    for (int s = 0; s < 3; s++) {
        CP_ASYNC16(dA0 + s * STAGE_B, srcA + s * 16);
        CP_ASYNC16(dB0 + s * STAGE_B, srcB + s * 16);
        CP_COMMIT();
    }

    for (int kc = 0; kc < 8; kc++) {
        CP_WAIT2();
        __syncthreads();
        const int st = kc & 3;

#pragma unroll
        for (int ks = 0; ks < 2; ks++) {
            uint2 a02 = *reinterpret_cast<const uint2*>(&sA[st][rw + g][ks * 8 + tig2]);
            uint2 a13 = *reinterpret_cast<const uint2*>(&sA[st][rw + g + 8][ks * 8 + tig2]);
#pragma unroll
            for (int nb = 0; nb < 4; nb++) {
                const int cn = cw + nb * 8 + g;
                uint2 bb = *reinterpret_cast<const uint2*>(&sB[st][cn][ks * 8 + tig2]);
                mma16816(c[nb], a02.x, a13.x, a02.y, a13.y, bb.x, bb.y);
            }
        }

        if (kc + 3 < 8) {
            const int s = kc + 3, sl = s & 3;
            CP_ASYNC16(dA0 + sl * STAGE_B, srcA + s * 16);
            CP_ASYNC16(dB0 + sl * STAGE_B, srcB + s * 16);
        }
        CP_COMMIT();
    }

    // ---- V epilogue: plain [bh][j][d], coalesced half2 stores ----
    const int b    = mBase >> 11;
    const int hloc = (mBase & 2047) >> 8;
    const int bh   = b * Hh + hloc;
    const int r255 = mBase & 255;
    const int cb   = (nBase >> 5) + wc;
    const int m0   = r255 + wr * 16 + g;

#pragma unroll
    for (int rq = 0; rq < 2; rq++) {
        const int jn = (m0 + rq * 8) * 8 + cb;
        __half* vrow = g_Vh16 + ((size_t)bh * 2048 + jn) * 32 + tig2;
#pragma unroll
        for (int nb = 0; nb < 4; nb++) {
            *reinterpret_cast<__half2*>(vrow + nb * 8) =
                __floats2half2_rn(c[nb][rq * 2], c[nb][rq * 2 + 1]);
        }
    }
}

// ---------------------------------------------------------------------------
// K2: fused scores (h2, MUFU-free) + HMMA PV (B-frags via ldmatrix.trans)
// + ones-MMA l + ELU. grid (32, 8, 4), 128 threads, double-buffered.
// V smem: [j][d] rows padded to 80 B (20 words) -> conflict-free LDSM.
// ---------------------------------------------------------------------------
__global__ __launch_bounds__(128) void attn_kernel(float* __restrict__ out) {
    __shared__ uint32_t sRowE[64];
    __shared__ __align__(8) uint32_t sF1[2][64];
    __shared__ __align__(8) uint32_t sF2[2][64];
    __shared__ uint4  sBits[2][64];
    __shared__ __align__(16) uint32_t sVt[2][128 * 20];

    const int tid  = threadIdx.x;
    const int w    = tid >> 5, lane = tid & 31;
    const int tig  = lane & 3, grp = lane >> 2;
    const int iT = blockIdx.x, hh = blockIdx.y, b = blockIdx.z;
    const int bh = b * Hh + hh;
    const int iBase = iT * 64;
    const int il0 = w * 16 + grp, il1 = il0 + 8;
    const int ipt = ipos(tid);

    const float wmax = fkeyinv(g_w2maxU[bh]);
    if (tid < 64) {
        float C = g_wh1s[bh * Nv + iBase + tid];
        float s = C + wmax;
        float M = fmaxf(s, SLOPE * s);
        sRowE[tid] = packh2(ex2f(s - M), ex2f(SLOPE * s - M));
    }

    const unsigned* bitsBase = g_adjbits + (size_t)(b * 2048 + iBase) * 64;
    const float* wh2Base = g_wh2s + (size_t)bh * 2048;
    const uint4* vBase = reinterpret_cast<const uint4*>(g_Vh16 + (size_t)bh * 2048 * 32);
    const int s0 = tig * 2, tig2 = tig * 2;

    const int laneRow = (lane & 7) + ((lane >> 3) & 1) * 8;
    const uint32_t laneOff = (uint32_t)(laneRow * 80 + (lane >> 4) * 16);
    const uint32_t vAddr[2] = { smem_u32(&sVt[0][0]) + laneOff,
                                smem_u32(&sVt[1][0]) + laneOff };

    {   // prefetch tile 0
        uint32_t* dst = sVt[0];
#pragma unroll
        for (int k = 0; k < 4; k++) {
            int idx = tid + k * 128;
            reinterpret_cast<uint4*>(dst)[(idx >> 2) * 5 + (idx & 3)] = vBase[idx];
        }
        float w2 = wh2Base[tid] - wmax;
        reinterpret_cast<__half*>(sF1[0])[ipt] = __float2half(ex2f(w2));
        reinterpret_cast<__half*>(sF2[0])[ipt] = __float2half(ex2f(SLOPE * w2));
        if (tid < 64)
            sBits[0][tid] = *reinterpret_cast<const uint4*>(bitsBase + (size_t)tid * 64);
    }
    __syncthreads();

    const uint32_t e0 = sRowE[il0], e1 = sRowE[il1];
    const uint32_t E0lo = prmtu(e0, e0, 0x1010u), E0hi = prmtu(e0, e0, 0x3232u);
    const uint32_t E1lo = prmtu(e1, e1, 0x1010u), E1hi = prmtu(e1, e1, 0x3232u);

    float dacc[4][4];
#pragma unroll
    for (int nb = 0; nb < 4; nb++)
#pragma unroll
        for (int q = 0; q < 4; q++) dacc[nb][q] = 0.f;
    float lacc[4] = {0.f, 0.f, 0.f, 0.f};

    int buf = 0;
    for (int jt = 0; jt < 16; jt++) {
        const int nj = (jt + 1) & 15;
        uint4 va[4];
#pragma unroll
        for (int k = 0; k < 4; k++) va[k] = vBase[nj * 512 + tid + k * 128];
        float w2n = wh2Base[nj * 128 + tid] - wmax;
        uint4 bqn = make_uint4(0, 0, 0, 0);
        if (tid < 64)
            bqn = *reinterpret_cast<const uint4*>(bitsBase + (size_t)tid * 64 + nj * 4);

        const uint4 bq0 = sBits[buf][il0];
        const uint4 bq1 = sBits[buf][il1];
        const unsigned* bw0w = reinterpret_cast<const unsigned*>(&bq0);
        const unsigned* bw1w = reinterpret_cast<const unsigned*>(&bq1);
        const uint32_t* F1p = sF1[buf];
        const uint32_t* F2p = sF2[buf];
        const uint32_t vA = vAddr[buf];

#pragma unroll
        for (int k2 = 0; k2 < 4; k2++) {
            const unsigned u0 = bw0w[k2] >> s0;
            const unsigned u1 = bw1w[k2] >> s0;
            const unsigned v07 = u0 << 7, v06 = u0 << 6;
            const unsigned v17 = u1 << 7, v16 = u1 << 6;
#pragma unroll
            for (int kh = 0; kh < 2; kh++) {
                const int ks = k2 * 2 + kh;
                const int wofs = ks * 8 + tig2;
                const uint2 f1 = *reinterpret_cast<const uint2*>(F1p + wofs);
                const uint2 f2 = *reinterpret_cast<const uint2*>(F2p + wofs);
                const uint32_t cA = kh ? 0xEEAAu : 0xCC88u;
                const uint32_t cB = kh ? 0xFFBBu : 0xDD99u;

                uint32_t A0 = hmax2u(hmul2u(E0lo, f1.x), hmul2u(E0hi, f2.x)) & prmtu(v07, v06, cA);
                uint32_t A2 = hmax2u(hmul2u(E0lo, f1.y), hmul2u(E0hi, f2.y)) & prmtu(v07, v06, cB);
                uint32_t A1 = hmax2u(hmul2u(E1lo, f1.x), hmul2u(E1hi, f2.x)) & prmtu(v17, v16, cA);
                uint32_t A3 = hmax2u(hmul2u(E1lo, f1.y), hmul2u(E1hi, f2.y)) & prmtu(v17, v16, cB);

                const uint32_t rowAddr = vA + (uint32_t)(ks * 16 * 80);
                uint32_t b0, b1, b2, b3;
                LDSM4T(b0, b1, b2, b3, rowAddr);
                mma16816(dacc[0], A0, A1, A2, A3, b0, b1);
                mma16816(dacc[1], A0, A1, A2, A3, b2, b3);
                LDSM4T(b0, b1, b2, b3, rowAddr + 32);
                mma16816(dacc[2], A0, A1, A2, A3, b0, b1);
                mma16816(dacc[3], A0, A1, A2, A3, b2, b3);
                mma16816(lacc, A0, A1, A2, A3, ONESH2, ONESH2);
            }
        }

        {   // stage next tile
            uint32_t* dst = sVt[buf ^ 1];
#pragma unroll
            for (int k = 0; k < 4; k++) {
                int idx = tid + k * 128;
                reinterpret_cast<uint4*>(dst)[(idx >> 2) * 5 + (idx & 3)] = va[k];
            }
            reinterpret_cast<__half*>(sF1[buf ^ 1])[ipt] = __float2half(ex2f(w2n));
            reinterpret_cast<__half*>(sF2[buf ^ 1])[ipt] = __float2half(ex2f(SLOPE * w2n));
            if (tid < 64) sBits[buf ^ 1][tid] = bqn;
        }
        __syncthreads();
        buf ^= 1;
    }

    const float rl0 = 1.f / lacc[0];
    const float rl1 = 1.f / lacc[2];

    const size_t o0 = ((size_t)bh * Nv + iBase + il0) * NHv + tig * 2;
    const size_t o1 = ((size_t)bh * Nv + iBase + il1) * NHv + tig * 2;
#pragma unroll
    for (int nb = 0; nb < 4; nb++) {
        float x0 = dacc[nb][0] * rl0, x1 = dacc[nb][1] * rl0;
        float y0 = dacc[nb][2] * rl1, y1 = dacc[nb][3] * rl1;
        x0 = (x0 > 0.f) ? x0 : expm1f(x0);
        x1 = (x1 > 0.f) ? x1 : expm1f(x1);
        y0 = (y0 > 0.f) ? y0 : expm1f(y0);
        y1 = (y1 > 0.f) ? y1 : expm1f(y1);
        *reinterpret_cast<float2*>(&out[o0 + nb * 8]) = make_float2(x0, x1);
        *reinterpret_cast<float2*>(&out[o1 + nb * 8]) = make_float2(y0, y1);
    }
}

// ---------------------------------------------------------------------------
extern "C" void kernel_launch(void* const* d_in, const int* in_sizes, int n_in,
                              void* d_out, int out_size) {
    const float* h   = (const float*)d_in[0];   // [4,2048,256]
    const int*   adj = (const int*)  d_in[1];   // [4,2048,2048]
    const float* W   = (const float*)d_in[2];   // [256,256]
    const float* a   = (const float*)d_in[3];   // [64,1]
    float* out = (float*)d_out;                 // [4,2048,256]

    static cudaStream_t s2 = nullptr, s3 = nullptr;
    static cudaEvent_t evFork = nullptr, evU = nullptr, evJ2 = nullptr, evJ3 = nullptr;
    if (s2 == nullptr) {
        cudaStreamCreateWithFlags(&s2, cudaStreamNonBlocking);
        cudaStreamCreateWithFlags(&s3, cudaStreamNonBlocking);
        cudaEventCreateWithFlags(&evFork, cudaEventDisableTiming);
        cudaEventCreateWithFlags(&evU, cudaEventDisableTiming);
        cudaEventCreateWithFlags(&evJ2, cudaEventDisableTiming);
        cudaEventCreateWithFlags(&evJ3, cudaEventDisableTiming);
    }

    // fork adjbits immediately (persistent, 2 blocks/SM ->真 concurrent)
    cudaEventRecord(evFork, 0);
    cudaStreamWaitEvent(s2, evFork, 0);
    adjbits_kernel<<<ADJ_BLOCKS, 256, 0, s2>>>((const int4*)adj);
    cudaEventRecord(evJ2, s2);

    // u (+hconv) first: produces g_U, g_Wh16t, g_Ah16
    u_kernel<<<528, 256>>>((const float4*)W, a, (const float4*)h);
    cudaEventRecord(evU, 0);

    // wh12 (fma-bound) on s3, concurrent with gemm (tensor-bound) on main
    cudaStreamWaitEvent(s3, evU, 0);
    wh12_kernel<<<512, 256, 0, s3>>>((const float4*)h);
    cudaEventRecord(evJ3, s3);

    gemm_f16_kernel<<<dim3(128, 4), 256>>>();

    // join: attn needs all branches
    cudaStreamWaitEvent(0, evJ2, 0);
    cudaStreamWaitEvent(0, evJ3, 0);
    attn_kernel<<<dim3(32, 8, 4), 128>>>(out);
}